// round 2
// baseline (speedup 1.0000x reference)
#include <cuda_runtime.h>
#include <cuda_bf16.h>

// EdgeConv: out[n] = A[n] - min_{src in in(n)} T[src]
//   T = feat @ W_theta
//   A = feat @ (W_theta + W_phi) + (b_theta + b_phi)
// CSR-by-dst built per call (deterministic output: min is order-independent).
// src/dst are int32 (JAX downgrades int64 without x64 mode).

#define D 64
#define MAX_N 50000
#define MAX_E 800000

__device__ float g_T[MAX_N * D];
__device__ float g_A[MAX_N * D];
__device__ int   g_deg[MAX_N];
__device__ int   g_offs[MAX_N + 1];
__device__ int   g_cursor[MAX_N];
__device__ int   g_esrc[MAX_E];

// ---------------------------------------------------------------------------
// Fused dual GEMM: T and A in one pass over feat. 32 rows/block, 256 threads.
// Thread (rg,d) computes 8 rows x 1 col for both accumulators.
// ---------------------------------------------------------------------------
__global__ void __launch_bounds__(256) gemm_kernel(
    const float* __restrict__ feat,
    const float* __restrict__ Wt, const float* __restrict__ bt,
    const float* __restrict__ Wp, const float* __restrict__ bp,
    int N)
{
    __shared__ float wt_s[D * D];
    __shared__ float wp_s[D * D];
    __shared__ float f_s[32 * D];

    int tid = threadIdx.x;
    for (int i = tid; i < D * D; i += 256) { wt_s[i] = Wt[i]; wp_s[i] = Wp[i]; }

    int row0 = blockIdx.x * 32;
    for (int i = tid; i < 32 * D; i += 256) {
        int r = row0 + (i >> 6);
        f_s[i] = (r < N) ? feat[r * D + (i & 63)] : 0.0f;
    }
    __syncthreads();

    int d  = tid & 63;
    int rg = tid >> 6;   // 0..3 -> rows rg*8 .. rg*8+7

    float at[8], ap[8];
#pragma unroll
    for (int r = 0; r < 8; r++) { at[r] = 0.0f; ap[r] = 0.0f; }

#pragma unroll
    for (int k = 0; k < D; k++) {
        float wt = wt_s[k * D + d];
        float wp = wp_s[k * D + d];
#pragma unroll
        for (int r = 0; r < 8; r++) {
            float f = f_s[(rg * 8 + r) * D + k];
            at[r] = fmaf(f, wt, at[r]);
            ap[r] = fmaf(f, wp, ap[r]);
        }
    }

    float bsum = bt[d] + bp[d];
#pragma unroll
    for (int r = 0; r < 8; r++) {
        int row = row0 + rg * 8 + r;
        if (row < N) {
            float t = at[r];
            g_T[row * D + d] = t;
            g_A[row * D + d] = t + ap[r] + bsum;
        }
    }
}

// ---------------------------------------------------------------------------
// CSR build
// ---------------------------------------------------------------------------
__global__ void zero_deg_kernel(int N)
{
    int i = blockIdx.x * blockDim.x + threadIdx.x;
    if (i < N) g_deg[i] = 0;
}

__global__ void hist_kernel(const int* __restrict__ dst, int E, int N)
{
    int i = blockIdx.x * blockDim.x + threadIdx.x;
    if (i < E) {
        int dn = dst[i];
        if (dn >= 0 && dn < N) atomicAdd(&g_deg[dn], 1);
    }
}

// Single-block exclusive scan over deg -> offs, cursor. N up to 50000.
__global__ void __launch_bounds__(1024) scan_kernel(int N)
{
    __shared__ int buf[1024];
    __shared__ int carry_s;
    int tid = threadIdx.x;
    if (tid == 0) carry_s = 0;
    __syncthreads();

    for (int base = 0; base < N; base += 1024) {
        int i = base + tid;
        int v = (i < N) ? g_deg[i] : 0;
        buf[tid] = v;
        __syncthreads();
#pragma unroll
        for (int off = 1; off < 1024; off <<= 1) {
            int t = (tid >= off) ? buf[tid - off] : 0;
            __syncthreads();
            buf[tid] += t;
            __syncthreads();
        }
        int excl = buf[tid] - v;
        int tot  = buf[1023];
        int c    = carry_s;
        if (i < N) {
            g_offs[i]   = c + excl;
            g_cursor[i] = c + excl;
        }
        __syncthreads();
        if (tid == 0) carry_s = c + tot;
        __syncthreads();
    }
    if (tid == 0) g_offs[N] = carry_s;
}

__global__ void scatter_kernel(const int* __restrict__ src,
                               const int* __restrict__ dst, int E, int N)
{
    int i = blockIdx.x * blockDim.x + threadIdx.x;
    if (i < E) {
        int dn = dst[i];
        int sn = src[i];
        if (dn >= 0 && dn < N && sn >= 0 && sn < N) {
            int pos = atomicAdd(&g_cursor[dn], 1);
            if (pos < MAX_E) g_esrc[pos] = sn;
        }
    }
}

// ---------------------------------------------------------------------------
// Gather: segment-min of T rows, out = A[n] - min. 8 nodes/block, 32 thr/node,
// float2 per lane -> one 256B coalesced row load per edge.
// ---------------------------------------------------------------------------
__global__ void __launch_bounds__(256) gather_kernel(float* __restrict__ out, int N)
{
    int node = blockIdx.x * 8 + (threadIdx.x >> 5);
    int lane = threadIdx.x & 31;
    if (node >= N) return;

    int start = g_offs[node];
    int end   = g_offs[node + 1];

    const float2* __restrict__ T2 = (const float2*)g_T;
    float mx = 3.402823466e+38f, my = 3.402823466e+38f;

#pragma unroll 4
    for (int j = start; j < end; j++) {
        int s = g_esrc[j];
        float2 v = T2[s * 32 + lane];
        mx = fminf(mx, v.x);
        my = fminf(my, v.y);
    }

    const float2* __restrict__ A2 = (const float2*)g_A;
    float2 a = A2[node * 32 + lane];
    float2 o;
    o.x = a.x - mx;
    o.y = a.y - my;
    ((float2*)out)[node * 32 + lane] = o;
}

// ---------------------------------------------------------------------------
extern "C" void kernel_launch(void* const* d_in, const int* in_sizes, int n_in,
                              void* d_out, int out_size)
{
    const float* feat = (const float*)d_in[0];
    const int*   src  = (const int*)d_in[1];
    const int*   dst  = (const int*)d_in[2];
    const float* Wt   = (const float*)d_in[3];
    const float* bt   = (const float*)d_in[4];
    const float* Wp   = (const float*)d_in[5];
    const float* bp   = (const float*)d_in[6];
    float*       out  = (float*)d_out;

    int N = in_sizes[0] / D;
    int E = in_sizes[1];

    zero_deg_kernel<<<(N + 255) / 256, 256>>>(N);
    hist_kernel<<<(E + 255) / 256, 256>>>(dst, E, N);
    gemm_kernel<<<(N + 31) / 32, 256>>>(feat, Wt, bt, Wp, bp, N);
    scan_kernel<<<1, 1024>>>(N);
    scatter_kernel<<<(E + 255) / 256, 256>>>(src, dst, E, N);
    gather_kernel<<<(N + 7) / 8, 256>>>(out, N);
}

// round 3
// speedup vs baseline: 1.9063x; 1.9063x over previous
#include <cuda_runtime.h>
#include <cuda_bf16.h>

// EdgeConv: out[n] = A[n] - min_{src in in(n)} T[src]
//   T = feat @ W_theta
//   A = feat @ (W_theta + W_phi) + (b_theta + b_phi)
// CSR-by-dst built per call (deterministic output: min is order-independent).
// src/dst are int32.

#define D 64
#define MAX_N 50000
#define MAX_E 800000
#define SCAN_BLK 1024
#define MAX_NB ((MAX_N + SCAN_BLK - 1) / SCAN_BLK)   // 49

__device__ float g_T[MAX_N * D];
__device__ float g_A[MAX_N * D];
__device__ int   g_deg[MAX_N];
__device__ int   g_offs[MAX_N + 1];
__device__ int   g_cursor[MAX_N];
__device__ int   g_esrc[MAX_E];
__device__ int   g_bsums[MAX_NB];
__device__ int   g_bpre[MAX_NB];

// ---------------------------------------------------------------------------
// Fused dual GEMM: T and A in one pass over feat. 32 rows/block, 256 threads.
// ---------------------------------------------------------------------------
__global__ void __launch_bounds__(256) gemm_kernel(
    const float* __restrict__ feat,
    const float* __restrict__ Wt, const float* __restrict__ bt,
    const float* __restrict__ Wp, const float* __restrict__ bp,
    int N)
{
    __shared__ float wt_s[D * D];
    __shared__ float wp_s[D * D];
    __shared__ float f_s[32 * D];

    int tid = threadIdx.x;
    for (int i = tid; i < D * D; i += 256) { wt_s[i] = Wt[i]; wp_s[i] = Wp[i]; }

    int row0 = blockIdx.x * 32;
    for (int i = tid; i < 32 * D; i += 256) {
        int r = row0 + (i >> 6);
        f_s[i] = (r < N) ? feat[r * D + (i & 63)] : 0.0f;
    }
    __syncthreads();

    int d  = tid & 63;
    int rg = tid >> 6;

    float at[8], ap[8];
#pragma unroll
    for (int r = 0; r < 8; r++) { at[r] = 0.0f; ap[r] = 0.0f; }

#pragma unroll
    for (int k = 0; k < D; k++) {
        float wt = wt_s[k * D + d];
        float wp = wp_s[k * D + d];
#pragma unroll
        for (int r = 0; r < 8; r++) {
            float f = f_s[(rg * 8 + r) * D + k];
            at[r] = fmaf(f, wt, at[r]);
            ap[r] = fmaf(f, wp, ap[r]);
        }
    }

    float bsum = bt[d] + bp[d];
#pragma unroll
    for (int r = 0; r < 8; r++) {
        int row = row0 + rg * 8 + r;
        if (row < N) {
            float t = at[r];
            g_T[row * D + d] = t;
            g_A[row * D + d] = t + ap[r] + bsum;
        }
    }
}

// ---------------------------------------------------------------------------
// CSR build
// ---------------------------------------------------------------------------
__global__ void zero_deg_kernel(int N)
{
    int i = blockIdx.x * blockDim.x + threadIdx.x;
    if (i < N) g_deg[i] = 0;
}

__global__ void hist_kernel(const int* __restrict__ dst, int E, int N)
{
    int i = blockIdx.x * blockDim.x + threadIdx.x;
    if (i < E) {
        int dn = dst[i];
        if (dn >= 0 && dn < N) atomicAdd(&g_deg[dn], 1);
    }
}

// --- hierarchical scan: 49 blocks x 1024 -> 49 sums -> fixup ---------------
__global__ void __launch_bounds__(SCAN_BLK) scan_blocks_kernel(int N)
{
    __shared__ int warp_sums[32];
    int tid  = threadIdx.x;
    int lane = tid & 31;
    int wid  = tid >> 5;
    int i    = blockIdx.x * SCAN_BLK + tid;

    int v = (i < N) ? g_deg[i] : 0;

    // warp inclusive scan
    int incl = v;
#pragma unroll
    for (int off = 1; off < 32; off <<= 1) {
        int t = __shfl_up_sync(0xffffffffu, incl, off);
        if (lane >= off) incl += t;
    }
    if (lane == 31) warp_sums[wid] = incl;
    __syncthreads();

    // scan the 32 warp sums in warp 0
    if (wid == 0) {
        int ws = warp_sums[lane];
        int wincl = ws;
#pragma unroll
        for (int off = 1; off < 32; off <<= 1) {
            int t = __shfl_up_sync(0xffffffffu, wincl, off);
            if (lane >= off) wincl += t;
        }
        warp_sums[lane] = wincl - ws;   // exclusive warp prefix
        if (lane == 31) g_bsums[blockIdx.x] = wincl;  // block total
    }
    __syncthreads();

    if (i < N) g_offs[i] = incl - v + warp_sums[wid];  // block-local exclusive
}

__global__ void scan_tops_kernel(int NB, int N)
{
    // single warp scans NB (<=49) block sums
    int lane = threadIdx.x;
    int carry = 0;
    for (int base = 0; base < NB; base += 32) {
        int idx = base + lane;
        int v = (idx < NB) ? g_bsums[idx] : 0;
        int incl = v;
#pragma unroll
        for (int off = 1; off < 32; off <<= 1) {
            int t = __shfl_up_sync(0xffffffffu, incl, off);
            if (lane >= off) incl += t;
        }
        if (idx < NB) g_bpre[idx] = carry + incl - v;
        carry += __shfl_sync(0xffffffffu, incl, 31);
    }
    if (lane == 0) g_offs[N] = carry;
}

__global__ void __launch_bounds__(SCAN_BLK) scan_fixup_kernel(int N)
{
    int i = blockIdx.x * SCAN_BLK + threadIdx.x;
    if (i < N) {
        int o = g_offs[i] + g_bpre[blockIdx.x];
        g_offs[i]   = o;
        g_cursor[i] = o;
    }
}

__global__ void scatter_kernel(const int* __restrict__ src,
                               const int* __restrict__ dst, int E, int N)
{
    int i = blockIdx.x * blockDim.x + threadIdx.x;
    if (i < E) {
        int dn = dst[i];
        int sn = src[i];
        if (dn >= 0 && dn < N && sn >= 0 && sn < N) {
            int pos = atomicAdd(&g_cursor[dn], 1);
            if (pos < MAX_E) g_esrc[pos] = sn;
        }
    }
}

// ---------------------------------------------------------------------------
// Gather: segment-min of T rows, out = A[n] - min. 8 nodes/block, 32 thr/node,
// float2 per lane -> one 256B coalesced row load per edge.
// ---------------------------------------------------------------------------
__global__ void __launch_bounds__(256) gather_kernel(float* __restrict__ out, int N)
{
    int node = blockIdx.x * 8 + (threadIdx.x >> 5);
    int lane = threadIdx.x & 31;
    if (node >= N) return;

    int start = g_offs[node];
    int end   = g_offs[node + 1];

    const float2* __restrict__ T2 = (const float2*)g_T;
    float mx = 3.402823466e+38f, my = 3.402823466e+38f;

#pragma unroll 4
    for (int j = start; j < end; j++) {
        int s = g_esrc[j];
        float2 v = T2[s * 32 + lane];
        mx = fminf(mx, v.x);
        my = fminf(my, v.y);
    }

    const float2* __restrict__ A2 = (const float2*)g_A;
    float2 a = A2[node * 32 + lane];
    float2 o;
    o.x = a.x - mx;
    o.y = a.y - my;
    ((float2*)out)[node * 32 + lane] = o;
}

// ---------------------------------------------------------------------------
extern "C" void kernel_launch(void* const* d_in, const int* in_sizes, int n_in,
                              void* d_out, int out_size)
{
    const float* feat = (const float*)d_in[0];
    const int*   src  = (const int*)d_in[1];
    const int*   dst  = (const int*)d_in[2];
    const float* Wt   = (const float*)d_in[3];
    const float* bt   = (const float*)d_in[4];
    const float* Wp   = (const float*)d_in[5];
    const float* bp   = (const float*)d_in[6];
    float*       out  = (float*)d_out;

    int N = in_sizes[0] / D;
    int E = in_sizes[1];
    int NB = (N + SCAN_BLK - 1) / SCAN_BLK;

    zero_deg_kernel<<<(N + 255) / 256, 256>>>(N);
    hist_kernel<<<(E + 255) / 256, 256>>>(dst, E, N);
    gemm_kernel<<<(N + 31) / 32, 256>>>(feat, Wt, bt, Wp, bp, N);
    scan_blocks_kernel<<<NB, SCAN_BLK>>>(N);
    scan_tops_kernel<<<1, 32>>>(NB, N);
    scan_fixup_kernel<<<NB, SCAN_BLK>>>(N);
    scatter_kernel<<<(E + 255) / 256, 256>>>(src, dst, E, N);
    gather_kernel<<<(N + 7) / 8, 256>>>(out, N);
}

// round 7
// speedup vs baseline: 2.2161x; 1.1625x over previous
#include <cuda_runtime.h>
#include <cuda_bf16.h>

// EdgeConv: out[n] = A[n] - min_{src in in(n)} T[src]
//   T = feat @ W_theta
//   A = feat @ (W_theta + W_phi) + (b_theta + b_phi)
// CSR-by-dst built per call. src/dst int32.
// GEMM uses packed fma.rn.f32x2 (2x fma-pipe throughput vs scalar FFMA).

#define D 64
#define MAX_N 50000
#define MAX_E 800000
#define SCAN_BLK 1024
#define MAX_NB ((MAX_N + SCAN_BLK - 1) / SCAN_BLK)

__device__ float g_T[MAX_N * D];
__device__ float g_A[MAX_N * D];
__device__ int   g_deg[MAX_N];
__device__ int   g_offs[MAX_N + 1];
__device__ int   g_cursor[MAX_N];
__device__ int   g_esrc[MAX_E];
__device__ int   g_bsums[MAX_NB];
__device__ int   g_bpre[MAX_NB];

// ---- f32x2 packed helpers --------------------------------------------------
__device__ __forceinline__ unsigned long long pack2(float x, float y) {
    unsigned long long r;
    asm("mov.b64 %0, {%1, %2};" : "=l"(r) : "f"(x), "f"(y));
    return r;
}
__device__ __forceinline__ void unpack2(unsigned long long v, float& x, float& y) {
    asm("mov.b64 {%0, %1}, %2;" : "=f"(x), "=f"(y) : "l"(v));
}
__device__ __forceinline__ void fma2(unsigned long long& d,
                                     unsigned long long a, unsigned long long b) {
    asm("fma.rn.f32x2 %0, %1, %2, %0;" : "+l"(d) : "l"(a), "l"(b));
}

// ---------------------------------------------------------------------------
// Dual GEMM, FFMA2 version. 64 rows/block, 256 threads.
// Thread (rg, dp): 8 rows x d-pair (2dp, 2dp+1) for both T and A accumulators.
// ---------------------------------------------------------------------------
__global__ void __launch_bounds__(256) gemm_kernel(
    const float* __restrict__ feat,
    const float* __restrict__ Wt, const float* __restrict__ bt,
    const float* __restrict__ Wp, const float* __restrict__ bp,
    int N)
{
    __shared__ float4 ws[D * 32];        // ws[k*32+dp] = (wt0, wt1, wp0, wp1)
    __shared__ float  f_s[64 * D];       // 64 rows x 64 k

    int tid = threadIdx.x;
    int row0 = blockIdx.x * 64;

    // weights: interleave Wt/Wp pairs
    {
        const float2* wt2 = (const float2*)Wt;
        const float2* wp2 = (const float2*)Wp;
        for (int i = tid; i < D * 32; i += 256) {
            float2 a = wt2[i];
            float2 b = wp2[i];
            ws[i] = make_float4(a.x, a.y, b.x, b.y);
        }
    }
    // feat tile: float4 loads, zero-fill OOB rows
    {
        float4* f4 = (float4*)f_s;
        const float4* feat4 = (const float4*)feat;
        for (int i = tid; i < 64 * (D / 4); i += 256) {
            int r = row0 + i / (D / 4);
            f4[i] = (r < N) ? feat4[(long)r * (D / 4) + (i & (D / 4 - 1))]
                            : make_float4(0.f, 0.f, 0.f, 0.f);
        }
    }
    __syncthreads();

    int dp = tid & 31;       // d-pair index
    int rg = tid >> 5;       // row group 0..7

    unsigned long long at[8], ap[8];
#pragma unroll
    for (int r = 0; r < 8; r++) { at[r] = pack2(0.f, 0.f); ap[r] = pack2(0.f, 0.f); }

    const float2* f2p = (const float2*)f_s;

#pragma unroll
    for (int k = 0; k < D; k += 2) {
        float4 wa = ws[k * 32 + dp];
        float4 wb = ws[(k + 1) * 32 + dp];
        unsigned long long wt0 = pack2(wa.x, wa.y);
        unsigned long long wp0 = pack2(wa.z, wa.w);
        unsigned long long wt1 = pack2(wb.x, wb.y);
        unsigned long long wp1 = pack2(wb.z, wb.w);
#pragma unroll
        for (int r = 0; r < 8; r++) {
            float2 f = f2p[((rg * 8 + r) * D + k) >> 1];
            unsigned long long f0 = pack2(f.x, f.x);
            unsigned long long f1 = pack2(f.y, f.y);
            fma2(at[r], f0, wt0);
            fma2(ap[r], f0, wp0);
            fma2(at[r], f1, wt1);
            fma2(ap[r], f1, wp1);
        }
    }

    float bs0 = bt[2 * dp] + bp[2 * dp];
    float bs1 = bt[2 * dp + 1] + bp[2 * dp + 1];

    float2* T2 = (float2*)g_T;
    float2* A2 = (float2*)g_A;
#pragma unroll
    for (int r = 0; r < 8; r++) {
        int row = row0 + rg * 8 + r;
        if (row < N) {
            float tx, ty, px, py;
            unpack2(at[r], tx, ty);
            unpack2(ap[r], px, py);
            T2[row * 32 + dp] = make_float2(tx, ty);
            A2[row * 32 + dp] = make_float2(tx + px + bs0, ty + py + bs1);
        }
    }
}

// ---------------------------------------------------------------------------
// CSR build
// ---------------------------------------------------------------------------
__global__ void zero_deg_kernel(int N)
{
    int i = blockIdx.x * blockDim.x + threadIdx.x;
    if (i < N) g_deg[i] = 0;
}

__global__ void hist_kernel(const int* __restrict__ dst, int E, int N)
{
    int i = blockIdx.x * blockDim.x + threadIdx.x;
    if (i < E) {
        int dn = dst[i];
        if (dn >= 0 && dn < N) atomicAdd(&g_deg[dn], 1);
    }
}

__global__ void __launch_bounds__(SCAN_BLK) scan_blocks_kernel(int N)
{
    __shared__ int warp_sums[32];
    int tid  = threadIdx.x;
    int lane = tid & 31;
    int wid  = tid >> 5;
    int i    = blockIdx.x * SCAN_BLK + tid;

    int v = (i < N) ? g_deg[i] : 0;

    int incl = v;
#pragma unroll
    for (int off = 1; off < 32; off <<= 1) {
        int t = __shfl_up_sync(0xffffffffu, incl, off);
        if (lane >= off) incl += t;
    }
    if (lane == 31) warp_sums[wid] = incl;
    __syncthreads();

    if (wid == 0) {
        int ws_ = warp_sums[lane];
        int wincl = ws_;
#pragma unroll
        for (int off = 1; off < 32; off <<= 1) {
            int t = __shfl_up_sync(0xffffffffu, wincl, off);
            if (lane >= off) wincl += t;
        }
        warp_sums[lane] = wincl - ws_;
        if (lane == 31) g_bsums[blockIdx.x] = wincl;
    }
    __syncthreads();

    if (i < N) g_offs[i] = incl - v + warp_sums[wid];
}

__global__ void scan_tops_kernel(int NB, int N)
{
    int lane = threadIdx.x;
    int carry = 0;
    for (int base = 0; base < NB; base += 32) {
        int idx = base + lane;
        int v = (idx < NB) ? g_bsums[idx] : 0;
        int incl = v;
#pragma unroll
        for (int off = 1; off < 32; off <<= 1) {
            int t = __shfl_up_sync(0xffffffffu, incl, off);
            if (lane >= off) incl += t;
        }
        if (idx < NB) g_bpre[idx] = carry + incl - v;
        carry += __shfl_sync(0xffffffffu, incl, 31);
    }
    if (lane == 0) g_offs[N] = carry;
}

__global__ void __launch_bounds__(SCAN_BLK) scan_fixup_kernel(int N)
{
    int i = blockIdx.x * SCAN_BLK + threadIdx.x;
    if (i < N) {
        int o = g_offs[i] + g_bpre[blockIdx.x];
        g_offs[i]   = o;
        g_cursor[i] = o;
    }
}

__global__ void scatter_kernel(const int* __restrict__ src,
                               const int* __restrict__ dst, int E, int N)
{
    int i = blockIdx.x * blockDim.x + threadIdx.x;
    if (i < E) {
        int dn = dst[i];
        int sn = src[i];
        if (dn >= 0 && dn < N && sn >= 0 && sn < N) {
            int pos = atomicAdd(&g_cursor[dn], 1);
            if (pos < MAX_E) g_esrc[pos] = sn;
        }
    }
}

// ---------------------------------------------------------------------------
// Gather: segment-min of T rows, out = A[n] - min.
// ---------------------------------------------------------------------------
__global__ void __launch_bounds__(256) gather_kernel(float* __restrict__ out, int N)
{
    int node = blockIdx.x * 8 + (threadIdx.x >> 5);
    int lane = threadIdx.x & 31;
    if (node >= N) return;

    int start = g_offs[node];
    int end   = g_offs[node + 1];

    const float2* __restrict__ T2 = (const float2*)g_T;
    float mx = 3.402823466e+38f, my = 3.402823466e+38f;

#pragma unroll 4
    for (int j = start; j < end; j++) {
        int s = g_esrc[j];
        float2 v = T2[s * 32 + lane];
        mx = fminf(mx, v.x);
        my = fminf(my, v.y);
    }

    const float2* __restrict__ A2 = (const float2*)g_A;
    float2 a = A2[node * 32 + lane];
    float2 o;
    o.x = a.x - mx;
    o.y = a.y - my;
    ((float2*)out)[node * 32 + lane] = o;
}

// ---------------------------------------------------------------------------
extern "C" void kernel_launch(void* const* d_in, const int* in_sizes, int n_in,
                              void* d_out, int out_size)
{
    const float* feat = (const float*)d_in[0];
    const int*   src  = (const int*)d_in[1];
    const int*   dst  = (const int*)d_in[2];
    const float* Wt   = (const float*)d_in[3];
    const float* bt   = (const float*)d_in[4];
    const float* Wp   = (const float*)d_in[5];
    const float* bp   = (const float*)d_in[6];
    float*       out  = (float*)d_out;

    int N = in_sizes[0] / D;
    int E = in_sizes[1];
    int NB = (N + SCAN_BLK - 1) / SCAN_BLK;

    zero_deg_kernel<<<(N + 255) / 256, 256>>>(N);
    hist_kernel<<<(E + 255) / 256, 256>>>(dst, E, N);
    gemm_kernel<<<(N + 63) / 64, 256>>>(feat, Wt, bt, Wp, bp, N);
    scan_blocks_kernel<<<NB, SCAN_BLK>>>(N);
    scan_tops_kernel<<<1, 32>>>(NB, N);
    scan_fixup_kernel<<<NB, SCAN_BLK>>>(N);
    scatter_kernel<<<(E + 255) / 256, 256>>>(src, dst, E, N);
    gather_kernel<<<(N + 7) / 8, 256>>>(out, N);
}

// round 8
// speedup vs baseline: 2.4337x; 1.0982x over previous
#include <cuda_runtime.h>
#include <cuda_fp16.h>

// EdgeConv: out[n] = A[n] - min_{src in in(n)} T[src]
//   T = feat @ W_theta              (stored fp16 -> halves gather L2 traffic)
//   A = feat @ (W_theta + W_phi) + (b_theta + b_phi)   (fp32)
// 5 launches: zero | combo(gemm+hist) | scan(single-pass) | scatter | gather

#define D 64
#define MAX_N 50000
#define MAX_E 800000
#define SCAN_BLK 1024
#define MAX_NB ((MAX_N + SCAN_BLK - 1) / SCAN_BLK)

__device__ __half2 g_Th[MAX_N * 32];
__device__ float   g_A[MAX_N * D];
__device__ int     g_deg[MAX_N];
__device__ int     g_offs[MAX_N + 1];
__device__ int     g_cursor[MAX_N];
__device__ int     g_esrc[MAX_E];
__device__ int     g_bsums[MAX_NB];    // aggregate+1, 0 = not ready

// ---- f32x2 packed helpers --------------------------------------------------
__device__ __forceinline__ unsigned long long pack2(float x, float y) {
    unsigned long long r;
    asm("mov.b64 %0, {%1, %2};" : "=l"(r) : "f"(x), "f"(y));
    return r;
}
__device__ __forceinline__ void unpack2(unsigned long long v, float& x, float& y) {
    asm("mov.b64 {%0, %1}, %2;" : "=f"(x), "=f"(y) : "l"(v));
}
__device__ __forceinline__ void fma2(unsigned long long& d,
                                     unsigned long long a, unsigned long long b) {
    asm("fma.rn.f32x2 %0, %1, %2, %0;" : "+l"(d) : "l"(a), "l"(b));
}

// ---------------------------------------------------------------------------
// zero: deg[N] and bsums[NB]
// ---------------------------------------------------------------------------
__global__ void zero_kernel(int N, int NB)
{
    int i = blockIdx.x * blockDim.x + threadIdx.x;
    if (i < N) g_deg[i] = 0;
    else if (i < N + NB) g_bsums[i - N] = 0;
}

// ---------------------------------------------------------------------------
// Combo: blocks [0, G_gemm) run the dual FFMA2 GEMM (64 rows each),
//        blocks [G_gemm, ...) run the degree histogram. Independent work.
// ---------------------------------------------------------------------------
__global__ void __launch_bounds__(256) combo_kernel(
    const float* __restrict__ feat,
    const float* __restrict__ Wt, const float* __restrict__ bt,
    const float* __restrict__ Wp, const float* __restrict__ bp,
    const int* __restrict__ dst,
    int N, int E, int G_gemm)
{
    __shared__ float4 ws[D * 32];        // (wt0, wt1, wp0, wp1) per (k, dpair)
    __shared__ float  f_s[64 * D];

    if (blockIdx.x >= G_gemm) {
        // ---- histogram part ----
        int i = (blockIdx.x - G_gemm) * 256 + threadIdx.x;
        if (i < E) {
            int dn = dst[i];
            if (dn >= 0 && dn < N) atomicAdd(&g_deg[dn], 1);
        }
        return;
    }

    // ---- GEMM part ----
    int tid = threadIdx.x;
    int row0 = blockIdx.x * 64;

    {
        const float2* wt2 = (const float2*)Wt;
        const float2* wp2 = (const float2*)Wp;
        for (int i = tid; i < D * 32; i += 256) {
            float2 a = wt2[i];
            float2 b = wp2[i];
            ws[i] = make_float4(a.x, a.y, b.x, b.y);
        }
    }
    {
        float4* f4 = (float4*)f_s;
        const float4* feat4 = (const float4*)feat;
        for (int i = tid; i < 64 * (D / 4); i += 256) {
            int r = row0 + i / (D / 4);
            f4[i] = (r < N) ? feat4[(long)r * (D / 4) + (i & (D / 4 - 1))]
                            : make_float4(0.f, 0.f, 0.f, 0.f);
        }
    }
    __syncthreads();

    int dp = tid & 31;
    int rg = tid >> 5;

    unsigned long long at[8], ap[8];
#pragma unroll
    for (int r = 0; r < 8; r++) { at[r] = pack2(0.f, 0.f); ap[r] = pack2(0.f, 0.f); }

    const float2* f2p = (const float2*)f_s;

#pragma unroll
    for (int k = 0; k < D; k += 2) {
        float4 wa = ws[k * 32 + dp];
        float4 wb = ws[(k + 1) * 32 + dp];
        unsigned long long wt0 = pack2(wa.x, wa.y);
        unsigned long long wp0 = pack2(wa.z, wa.w);
        unsigned long long wt1 = pack2(wb.x, wb.y);
        unsigned long long wp1 = pack2(wb.z, wb.w);
#pragma unroll
        for (int r = 0; r < 8; r++) {
            float2 f = f2p[((rg * 8 + r) * D + k) >> 1];
            unsigned long long f0 = pack2(f.x, f.x);
            unsigned long long f1 = pack2(f.y, f.y);
            fma2(at[r], f0, wt0);
            fma2(ap[r], f0, wp0);
            fma2(at[r], f1, wt1);
            fma2(ap[r], f1, wp1);
        }
    }

    float bs0 = bt[2 * dp] + bp[2 * dp];
    float bs1 = bt[2 * dp + 1] + bp[2 * dp + 1];

    float2* A2 = (float2*)g_A;
#pragma unroll
    for (int r = 0; r < 8; r++) {
        int row = row0 + rg * 8 + r;
        if (row < N) {
            float tx, ty, px, py;
            unpack2(at[r], tx, ty);
            unpack2(ap[r], px, py);
            g_Th[row * 32 + dp] = __floats2half2_rn(tx, ty);
            A2[row * 32 + dp]   = make_float2(tx + px + bs0, ty + py + bs1);
        }
    }
}

// ---------------------------------------------------------------------------
// Single-pass scan. NB <= 148 blocks => all co-resident => safe to publish
// block aggregates and poll predecessors. Writes offs + cursor directly.
// ---------------------------------------------------------------------------
__global__ void __launch_bounds__(SCAN_BLK) scan_kernel(int N, int NB)
{
    __shared__ int warp_sums[32];
    __shared__ int s_agg;
    __shared__ int s_prefix;
    int tid  = threadIdx.x;
    int lane = tid & 31;
    int wid  = tid >> 5;
    int bid  = blockIdx.x;
    int i    = bid * SCAN_BLK + tid;

    int v = (i < N) ? g_deg[i] : 0;

    int incl = v;
#pragma unroll
    for (int off = 1; off < 32; off <<= 1) {
        int t = __shfl_up_sync(0xffffffffu, incl, off);
        if (lane >= off) incl += t;
    }
    if (lane == 31) warp_sums[wid] = incl;
    __syncthreads();

    if (wid == 0) {
        int ws_ = warp_sums[lane];
        int wincl = ws_;
#pragma unroll
        for (int off = 1; off < 32; off <<= 1) {
            int t = __shfl_up_sync(0xffffffffu, wincl, off);
            if (lane >= off) wincl += t;
        }
        warp_sums[lane] = wincl - ws_;
        if (lane == 31) {
            s_agg = wincl;
            atomicExch(&g_bsums[bid], wincl + 1);   // publish aggregate
        }
    }
    __syncthreads();

    // warp 0 gathers prefix = sum of aggregates of blocks [0, bid)
    if (wid == 0) {
        int sum = 0;
        for (int base = 0; base < bid; base += 32) {
            int j = base + lane;
            int val = 0;
            if (j < bid) {
                do { val = atomicAdd(&g_bsums[j], 0); } while (val == 0);
                val -= 1;
            }
            sum += val;
        }
#pragma unroll
        for (int off = 16; off >= 1; off >>= 1)
            sum += __shfl_xor_sync(0xffffffffu, sum, off);
        if (lane == 0) s_prefix = sum;
    }
    __syncthreads();

    int pre = s_prefix;
    if (i < N) {
        int o = incl - v + warp_sums[wid] + pre;
        g_offs[i]   = o;
        g_cursor[i] = o;
    }
    if (bid == NB - 1 && tid == 0) g_offs[N] = pre + s_agg;
}

__global__ void scatter_kernel(const int* __restrict__ src,
                               const int* __restrict__ dst, int E, int N)
{
    int i = blockIdx.x * blockDim.x + threadIdx.x;
    if (i < E) {
        int dn = dst[i];
        int sn = src[i];
        if (dn >= 0 && dn < N && sn >= 0 && sn < N) {
            int pos = atomicAdd(&g_cursor[dn], 1);
            if (pos < MAX_E) g_esrc[pos] = sn;
        }
    }
}

// ---------------------------------------------------------------------------
// Gather: segment-min of fp16 T rows, out = A[n] - min. One warp per node,
// one half2 (two dims) per lane -> 128B coalesced row load per edge.
// ---------------------------------------------------------------------------
__global__ void __launch_bounds__(256) gather_kernel(float* __restrict__ out, int N)
{
    int node = blockIdx.x * 8 + (threadIdx.x >> 5);
    int lane = threadIdx.x & 31;
    if (node >= N) return;

    int start = g_offs[node];
    int end   = g_offs[node + 1];

    __half2 m = __floats2half2_rn(65504.f, 65504.f);

#pragma unroll 4
    for (int j = start; j < end; j++) {
        int s = g_esrc[j];
        __half2 v = g_Th[s * 32 + lane];
        m = __hmin2(m, v);
    }

    float2 mf = __half22float2(m);
    const float2* __restrict__ A2 = (const float2*)g_A;
    float2 a = A2[node * 32 + lane];
    float2 o;
    o.x = a.x - mf.x;
    o.y = a.y - mf.y;
    ((float2*)out)[node * 32 + lane] = o;
}

// ---------------------------------------------------------------------------
extern "C" void kernel_launch(void* const* d_in, const int* in_sizes, int n_in,
                              void* d_out, int out_size)
{
    const float* feat = (const float*)d_in[0];
    const int*   src  = (const int*)d_in[1];
    const int*   dst  = (const int*)d_in[2];
    const float* Wt   = (const float*)d_in[3];
    const float* bt   = (const float*)d_in[4];
    const float* Wp   = (const float*)d_in[5];
    const float* bp   = (const float*)d_in[6];
    float*       out  = (float*)d_out;

    int N  = in_sizes[0] / D;
    int E  = in_sizes[1];
    int NB = (N + SCAN_BLK - 1) / SCAN_BLK;

    int G_gemm = (N + 63) / 64;
    int G_hist = (E + 255) / 256;

    zero_kernel<<<(N + NB + 255) / 256, 256>>>(N, NB);
    combo_kernel<<<G_gemm + G_hist, 256>>>(feat, Wt, bt, Wp, bp, dst, N, E, G_gemm);
    scan_kernel<<<NB, SCAN_BLK>>>(N, NB);
    scatter_kernel<<<(E + 255) / 256, 256>>>(src, dst, E, N);
    gather_kernel<<<(N + 7) / 8, 256>>>(out, N);
}